// round 16
// baseline (speedup 1.0000x reference)
#include <cuda_runtime.h>
#include <cuda_fp16.h>
#include <math.h>
#include <stdint.h>

#define D_MODEL 768
#define HEADS   12
#define HD      64
#define BATCH   4
#define SEQ     2048
#define M_TOTAL (BATCH*SEQ)      // 8192
#define N_QKV   (3*D_MODEL)      // 2304
#define BH      (BATCH*HEADS)    // 48
#define KDIM    768
#define NCHUNK  (KDIM/64)        // 12 chunks of K=64

// q scale: 1/sqrt(64) * log2(e)  (softmax done in exp2 domain)
#define QSCALE 0.1803368801111306f

// Scratch (device globals)
__device__ __half g_q[BH*SEQ*HD];       // pre-scaled by QSCALE
__device__ __half g_k[BH*SEQ*HD];
__device__ __half g_vt[BH*HD*SEQ];      // [bh][d][seq]
__device__ __half g_h[M_TOTAL*D_MODEL]; // half X, later attn output
__device__ __half g_wqkv_t[N_QKV*KDIM];
__device__ __half g_wout_t[D_MODEL*KDIM];

// ---------------------------------------------------------------------------
__device__ __forceinline__ uint32_t smem_to_u32(const void* p) {
    uint32_t a;
    asm("{ .reg .u64 t; cvta.to.shared.u64 t, %1; cvt.u32.u64 %0, t; }"
        : "=r"(a) : "l"(p));
    return a;
}
__device__ __forceinline__ uint32_t pack_half2(float lo, float hi) {
    uint32_t u;
    asm("cvt.rn.f16x2.f32 %0, %1, %2;" : "=r"(u) : "f"(hi), "f"(lo));
    return u;
}
__device__ __forceinline__ uint32_t exp2_h2(uint32_t a) {
    uint32_t d;
    asm("ex2.approx.f16x2 %0, %1;" : "=r"(d) : "r"(a));
    return d;
}
// sum of the two f16 halves of u, in f32 (exact unpack then FADD)
__device__ __forceinline__ float h2_sumf(uint32_t u) {
    half2 h = *(half2*)&u;
    float2 f = __half22float2(h);
    return f.x + f.y;
}
__device__ __forceinline__ void ldsm_x4(uint32_t& r0, uint32_t& r1,
                                        uint32_t& r2, uint32_t& r3, uint32_t addr)
{
    asm volatile("ldmatrix.sync.aligned.m8n8.x4.shared.b16 {%0,%1,%2,%3}, [%4];"
        : "=r"(r0), "=r"(r1), "=r"(r2), "=r"(r3) : "r"(addr));
}
#define CP_ASYNC16(smem_addr, gptr) \
    asm volatile("cp.async.cg.shared.global [%0], [%1], 16;" \
        :: "r"(smem_addr), "l"(gptr))
#define CP_COMMIT() asm volatile("cp.async.commit_group;" ::: "memory")
#define CP_WAIT1()  asm volatile("cp.async.wait_group 1;" ::: "memory")
#define CP_WAIT0()  asm volatile("cp.async.wait_group 0;" ::: "memory")

__device__ __forceinline__ void mma_f16(float c[4],
    uint32_t a0, uint32_t a1, uint32_t a2, uint32_t a3,
    uint32_t b0, uint32_t b1)
{
    asm volatile(
        "mma.sync.aligned.m16n8k16.row.col.f32.f16.f16.f32 "
        "{%0,%1,%2,%3}, {%4,%5,%6,%7}, {%8,%9}, {%0,%1,%2,%3};"
        : "+f"(c[0]), "+f"(c[1]), "+f"(c[2]), "+f"(c[3])
        : "r"(a0), "r"(a1), "r"(a2), "r"(a3), "r"(b0), "r"(b1));
}

// ---------------------------------------------------------------------------
// X -> half
__global__ void convert_x_kernel(const float* __restrict__ src, __half* __restrict__ dst)
{
    const int i = (blockIdx.x * blockDim.x + threadIdx.x) * 4;
    float4 v = *(const float4*)&src[i];
    ((uint32_t*)dst)[i/2]     = pack_half2(v.x, v.y);
    ((uint32_t*)dst)[i/2 + 1] = pack_half2(v.z, v.w);
}

// W transpose + half: dst[N][K] = half(src[K][N])
__global__ void transpose_w_kernel(const float* __restrict__ src,
                                   __half* __restrict__ dst, int R, int C)
{
    __shared__ float t[32][33];
    const int bx = blockIdx.x * 32, by = blockIdx.y * 32;
    const int x = threadIdx.x, y = threadIdx.y;
    #pragma unroll
    for (int i = 0; i < 32; i += 8)
        t[y + i][x] = src[(size_t)(by + y + i) * C + bx + x];
    __syncthreads();
    #pragma unroll
    for (int i = 0; i < 32; i += 8)
        dst[(size_t)(bx + y + i) * R + by + x] = __float2half_rn(t[x][y + i]);
}

// ---------------------------------------------------------------------------
// fp16 mma.sync GEMM: 128-thread CTAs (4 warps), tile 64m x 128n, 4 CTAs/SM.
// 2-stage cp.async, K chunks of 64, ldmatrix fragments. (R14, unchanged)
// MODE 0: scatter q(*QSCALE)/k to [bh][seq][64]; V transposed into g_vt.
// MODE 1: fp32 [M][768] out.
// ---------------------------------------------------------------------------
#define HPU   36                 // u32 per smem row (72 halfs, 64 used)
#define ABUF  (64*HPU)           // A stage: 2304 u32
#define BBUF  (128*HPU)          // B stage: 4608 u32
#define CPITCH 133               // floats, epilogue staging pitch

template<int MODE>
__global__ __launch_bounds__(128, 4)
void mma_gemm_kernel(const __half* __restrict__ A, const __half* __restrict__ Bt,
                     const float* __restrict__ bias, float* __restrict__ out)
{
    extern __shared__ uint32_t smu[];
    float* smf = (float*)smu;

    const int tid  = threadIdx.x;
    const int wid  = tid >> 5;
    const int lane = tid & 31;
    const int m0 = blockIdx.y * 64;
    const int n0 = blockIdx.x * 128;
    const int wm = (wid >> 1) * 32;
    const int wn = (wid & 1) * 64;
    const uint32_t sbase = smem_to_u32(smu);
    const int r = lane >> 2;
    const int cl = lane & 3;
    const int mm = lane >> 3;
    const int lrow = lane & 7;

    uint32_t aoff[2], boff[4];
    #pragma unroll
    for (int mi = 0; mi < 2; mi++)
        aoff[mi] = ((wm + mi*16 + (mm & 1)*8 + lrow) * HPU + (mm >> 1)*4) * 4;
    #pragma unroll
    for (int p = 0; p < 4; p++)
        boff[p] = ((wn + (p*2 + (mm >> 1))*8 + lrow) * HPU + (mm & 1)*4) * 4;

    float acc[2][8][4] = {};

    #pragma unroll
    for (int i = 0; i < 12; i++) {
        const int idx = i * 128 + tid;
        if (idx < 512) {
            const int row = idx >> 3;
            const int seg = (idx & 7) * 8;
            CP_ASYNC16(sbase + (uint32_t)(row*HPU)*4 + seg*2,
                       &A[(size_t)(m0 + row) * KDIM + seg]);
        } else {
            const int j = idx - 512;
            const int row = j >> 3;
            const int seg = (j & 7) * 8;
            CP_ASYNC16(sbase + (uint32_t)(2*ABUF + row*HPU)*4 + seg*2,
                       &Bt[(size_t)(n0 + row) * KDIM + seg]);
        }
    }
    CP_COMMIT();

    for (int c = 0; c < NCHUNK; c++) {
        const int buf = c & 1;
        if (c + 1 < NCHUNK) {
            const int nb = buf ^ 1;
            const int k0 = (c + 1) * 64;
            #pragma unroll
            for (int i = 0; i < 12; i++) {
                const int idx = i * 128 + tid;
                if (idx < 512) {
                    const int row = idx >> 3;
                    const int seg = (idx & 7) * 8;
                    CP_ASYNC16(sbase + (uint32_t)(nb*ABUF + row*HPU)*4 + seg*2,
                               &A[(size_t)(m0 + row) * KDIM + k0 + seg]);
                } else {
                    const int j = idx - 512;
                    const int row = j >> 3;
                    const int seg = (j & 7) * 8;
                    CP_ASYNC16(sbase + (uint32_t)(2*ABUF + nb*BBUF + row*HPU)*4 + seg*2,
                               &Bt[(size_t)(n0 + row) * KDIM + k0 + seg]);
                }
            }
            CP_COMMIT();
            CP_WAIT1();
        } else {
            CP_WAIT0();
        }
        __syncthreads();

        const uint32_t aB = sbase + (uint32_t)(buf*ABUF)*4;
        const uint32_t bB = sbase + (uint32_t)(2*ABUF + buf*BBUF)*4;

        #pragma unroll
        for (int ks = 0; ks < 4; ks++) {
            const uint32_t kbyte = ks * 32;
            uint32_t af[2][4];
            #pragma unroll
            for (int mi = 0; mi < 2; mi++)
                ldsm_x4(af[mi][0], af[mi][1], af[mi][2], af[mi][3],
                        aB + aoff[mi] + kbyte);
            uint32_t bf[8][2];
            #pragma unroll
            for (int p = 0; p < 4; p++)
                ldsm_x4(bf[2*p][0], bf[2*p][1], bf[2*p+1][0], bf[2*p+1][1],
                        bB + boff[p] + kbyte);
            #pragma unroll
            for (int mi = 0; mi < 2; mi++)
                #pragma unroll
                for (int ni = 0; ni < 8; ni++)
                    mma_f16(acc[mi][ni], af[mi][0], af[mi][1], af[mi][2], af[mi][3],
                            bf[ni][0], bf[ni][1]);
        }
        __syncthreads();
    }

    #pragma unroll
    for (int mi = 0; mi < 2; mi++)
        #pragma unroll
        for (int ni = 0; ni < 8; ni++) {
            const int row = wm + mi*16 + r;
            const int col = wn + ni*8 + 2*cl;
            smf[row * CPITCH + col]       = acc[mi][ni][0];
            smf[row * CPITCH + col + 1]   = acc[mi][ni][1];
            smf[(row+8) * CPITCH + col]   = acc[mi][ni][2];
            smf[(row+8) * CPITCH + col+1] = acc[mi][ni][3];
        }
    __syncthreads();

    if (MODE == 1) {
        #pragma unroll
        for (int i = 0; i < 16; i++) {
            const int f = i * 128 + tid;
            const int row  = f >> 5;
            const int col  = (f & 31) * 4;
            const int m  = m0 + row;
            const int ng = n0 + col;
            float4 v = { smf[row*CPITCH + col + 0] + bias[ng + 0],
                         smf[row*CPITCH + col + 1] + bias[ng + 1],
                         smf[row*CPITCH + col + 2] + bias[ng + 2],
                         smf[row*CPITCH + col + 3] + bias[ng + 3] };
            *(float4*)&out[(size_t)m * D_MODEL + ng] = v;
        }
    } else {
        const int wsel = n0 / D_MODEL;
        if (wsel < 2) {
            __half* dst = (wsel == 0) ? g_q : g_k;
            const float sc = (wsel == 0) ? QSCALE : 1.0f;
            #pragma unroll
            for (int i = 0; i < 16; i++) {
                const int f = i * 128 + tid;
                const int row  = f >> 5;
                const int col  = (f & 31) * 4;
                const int m  = m0 + row;
                const int ng = n0 + col;
                float4 v = { (smf[row*CPITCH + col + 0] + bias[ng + 0]) * sc,
                             (smf[row*CPITCH + col + 1] + bias[ng + 1]) * sc,
                             (smf[row*CPITCH + col + 2] + bias[ng + 2]) * sc,
                             (smf[row*CPITCH + col + 3] + bias[ng + 3]) * sc };
                const int h = (ng % D_MODEL) >> 6;
                const int d = ng & 63;
                const int bb = m >> 11;
                const int l  = m & (SEQ - 1);
                const size_t off = (((size_t)bb * HEADS + h) * SEQ + l) * HD + d;
                ((uint32_t*)dst)[off/2]     = pack_half2(v.x, v.y);
                ((uint32_t*)dst)[off/2 + 1] = pack_half2(v.z, v.w);
            }
        } else {
            const int bb = m0 >> 11;
            const int l0 = m0 & (SEQ - 1);
            #pragma unroll
            for (int it = 0; it < 32; it++) {
                const int idx = it * 128 + tid;
                const int d  = idx >> 5;
                const int l2 = idx & 31;
                const int ng = n0 + d;
                const float bv = bias[ng];
                const int h  = (ng % D_MODEL) >> 6;
                const int dd = ng & 63;
                const float v0 = smf[(2*l2)   * CPITCH + d] + bv;
                const float v1 = smf[(2*l2+1) * CPITCH + d] + bv;
                const size_t off = ((size_t)(bb * HEADS + h) * HD + dd) * SEQ + l0 + 2*l2;
                ((uint32_t*)g_vt)[off/2] = pack_half2(v0, v1);
            }
        }
    }
}

// ---------------------------------------------------------------------------
// Flash attention: 128-thread CTAs (4 warps x 16q = 64 q rows), 4 CTAs/SM.
// 64-key tiles double-buffered (R14 shape). f16x2 exp2 softmax.
// Row sums via exact f32 unpack-FADD of the f16 P fragments (fma pipe,
// keeping the saturated tensor pipe free). P in registers.
// ---------------------------------------------------------------------------
#define AKPU  36                 // u32 per 72-half row
#define KTU   (64*AKPU)          // 2304 u32 per K or VT tile

__global__ __launch_bounds__(128, 4) void attn_kernel(__half* __restrict__ attn_out)
{
    extern __shared__ uint32_t smA[];

    const int tid  = threadIdx.x;
    const int wid  = tid >> 5;
    const int lane = tid & 31;
    const int r  = lane >> 2;
    const int cl = lane & 3;
    const int mm = lane >> 3;
    const int lrow = lane & 7;
    const int qt = blockIdx.x;
    const int bh = blockIdx.y;
    const size_t head_base = (size_t)bh * SEQ * HD;   // halfs
    const int q0 = wid * 16;

    uint32_t foff[4];
    #pragma unroll
    for (int p = 0; p < 4; p++)
        foff[p] = (((p*2 + (mm >> 1))*8 + lrow) * AKPU + (mm & 1)*4) * 4;

    // Q fragments (g_q pre-scaled): 4 ksteps x 4 regs
    uint32_t qf[4][4];
    {
        const uint32_t* Qp = (const uint32_t*)&g_q[head_base + (size_t)(qt*64 + q0) * HD];
        #pragma unroll
        for (int kk = 0; kk < 4; kk++) {
            qf[kk][0] = Qp[(size_t)r     * 32 + kk*8 + cl];
            qf[kk][1] = Qp[(size_t)(r+8) * 32 + kk*8 + cl];
            qf[kk][2] = Qp[(size_t)r     * 32 + kk*8 + cl + 4];
            qf[kk][3] = Qp[(size_t)(r+8) * 32 + kk*8 + cl + 4];
        }
    }

    float o[8][4] = {};
    float mo0 = -INFINITY, mo1 = -INFINITY, lo0 = 0.0f, lo1 = 0.0f;

    const uint32_t sb = smem_to_u32(smA);
    // layout: [K0, V0, K1, V1]
    const uint32_t kb[2] = { sb,              sb + 2*KTU*4 };
    const uint32_t vb[2] = { sb + KTU*4,      sb + 3*KTU*4 };
    const size_t vt_base = (size_t)bh * HD * SEQ;

    // prologue tile 0: K 64x8 segs (512) + VT 64x8 segs (512) = 8/thread
    #pragma unroll
    for (int i = 0; i < 8; i++) {
        const int idx = i * 128 + tid;
        if (idx < 512) {
            const int row = idx >> 3;
            const int seg = (idx & 7) * 8;
            CP_ASYNC16(kb[0] + (uint32_t)(row*AKPU)*4 + seg*2,
                       (const char*)&g_k[head_base + (size_t)row * HD + seg]);
        } else {
            const int j = idx - 512;
            const int row = j >> 3;
            const int seg = (j & 7) * 8;
            CP_ASYNC16(vb[0] + (uint32_t)(row*AKPU)*4 + seg*2,
                       (const char*)&g_vt[vt_base + (size_t)row * SEQ + seg]);
        }
    }
    CP_COMMIT();

    for (int kt = 0; kt < SEQ/64; kt++) {
        const int buf = kt & 1;
        __syncthreads();   // done with buf^1
        if (kt + 1 < SEQ/64) {
            const int nb = buf ^ 1;
            #pragma unroll
            for (int i = 0; i < 8; i++) {
                const int idx = i * 128 + tid;
                if (idx < 512) {
                    const int row = idx >> 3;
                    const int seg = (idx & 7) * 8;
                    CP_ASYNC16(kb[nb] + (uint32_t)(row*AKPU)*4 + seg*2,
                               (const char*)&g_k[head_base + (size_t)((kt+1)*64 + row) * HD + seg]);
                } else {
                    const int j = idx - 512;
                    const int row = j >> 3;
                    const int seg = (j & 7) * 8;
                    CP_ASYNC16(vb[nb] + (uint32_t)(row*AKPU)*4 + seg*2,
                               (const char*)&g_vt[vt_base + (size_t)row * SEQ + (kt+1)*64 + seg]);
                }
            }
            CP_COMMIT();
            CP_WAIT1();
        } else {
            CP_WAIT0();
        }
        __syncthreads();   // tile kt visible

        // ---- S = Q K^T ----
        const uint32_t Kc = kb[buf];
        float s[8][4] = {};
        #pragma unroll
        for (int kk = 0; kk < 4; kk++) {
            const uint32_t kbyte = kk * 32;
            uint32_t bf[8][2];
            #pragma unroll
            for (int p = 0; p < 4; p++)
                ldsm_x4(bf[2*p][0], bf[2*p][1], bf[2*p+1][0], bf[2*p+1][1],
                        Kc + foff[p] + kbyte);
            #pragma unroll
            for (int nt = 0; nt < 8; nt++)
                mma_f16(s[nt], qf[kk][0], qf[kk][1], qf[kk][2], qf[kk][3],
                        bf[nt][0], bf[nt][1]);
        }

        // ---- row max (quad reduction) ----
        float mx0 = -INFINITY, mx1 = -INFINITY;
        #pragma unroll
        for (int nt = 0; nt < 8; nt++) {
            mx0 = fmaxf(mx0, fmaxf(s[nt][0], s[nt][1]));
            mx1 = fmaxf(mx1, fmaxf(s[nt][2], s[nt][3]));
        }
        mx0 = fmaxf(mx0, __shfl_xor_sync(0xffffffffu, mx0, 1));
        mx0 = fmaxf(mx0, __shfl_xor_sync(0xffffffffu, mx0, 2));
        mx1 = fmaxf(mx1, __shfl_xor_sync(0xffffffffu, mx1, 1));
        mx1 = fmaxf(mx1, __shfl_xor_sync(0xffffffffu, mx1, 2));
        const float mn0 = fmaxf(mo0, mx0);
        const float mn1 = fmaxf(mo1, mx1);
        const float a0 = exp2f(mo0 - mn0);
        const float a1 = exp2f(mo1 - mn1);

        // ---- P = exp2(s - m) in f16x2, packed as PV A-fragments ----
        uint32_t pf[4][4];
        #pragma unroll
        for (int kk = 0; kk < 4; kk++) {
            pf[kk][0] = exp2_h2(pack_half2(s[2*kk][0]   - mn0, s[2*kk][1]   - mn0));
            pf[kk][1] = exp2_h2(pack_half2(s[2*kk][2]   - mn1, s[2*kk][3]   - mn1));
            pf[kk][2] = exp2_h2(pack_half2(s[2*kk+1][0] - mn0, s[2*kk+1][1] - mn0));
            pf[kk][3] = exp2_h2(pack_half2(s[2*kk+1][2] - mn1, s[2*kk+1][3] - mn1));
        }

        // ---- row sums: exact f32 sums of the f16 P values (fma pipe) ----
        float sum0 = 0.0f, sum1 = 0.0f;
        #pragma unroll
        for (int kk = 0; kk < 4; kk++) {
            sum0 += h2_sumf(pf[kk][0]) + h2_sumf(pf[kk][2]);
            sum1 += h2_sumf(pf[kk][1]) + h2_sumf(pf[kk][3]);
        }
        sum0 += __shfl_xor_sync(0xffffffffu, sum0, 1);
        sum0 += __shfl_xor_sync(0xffffffffu, sum0, 2);
        sum1 += __shfl_xor_sync(0xffffffffu, sum1, 1);
        sum1 += __shfl_xor_sync(0xffffffffu, sum1, 2);

        lo0 = a0 * lo0 + sum0;  mo0 = mn0;
        lo1 = a1 * lo1 + sum1;  mo1 = mn1;
        #pragma unroll
        for (int nt = 0; nt < 8; nt++) {
            o[nt][0] *= a0; o[nt][1] *= a0;
            o[nt][2] *= a1; o[nt][3] *= a1;
        }

        // ---- O += P V ----
        const uint32_t Vc = vb[buf];
        #pragma unroll
        for (int kk = 0; kk < 4; kk++) {
            const uint32_t kbyte = kk * 32;
            uint32_t bf[8][2];
            #pragma unroll
            for (int p = 0; p < 4; p++)
                ldsm_x4(bf[2*p][0], bf[2*p][1], bf[2*p+1][0], bf[2*p+1][1],
                        Vc + foff[p] + kbyte);
            #pragma unroll
            for (int nt = 0; nt < 8; nt++)
                mma_f16(o[nt], pf[kk][0], pf[kk][1], pf[kk][2], pf[kk][3],
                        bf[nt][0], bf[nt][1]);
        }
    }

    // ---- epilogue: normalize, write half [B, L, H*64] ----
    const float inv0 = 1.0f / lo0;
    const float inv1 = 1.0f / lo1;
    const int bb = bh / HEADS;
    const int h  = bh % HEADS;
    const int row0 = qt*64 + q0 + r;
    #pragma unroll
    for (int nt = 0; nt < 8; nt++) {
        const int d = h * 64 + nt*8 + 2*cl;
        ((uint32_t*)attn_out)[(((size_t)bb * SEQ + row0)     * D_MODEL + d)/2] =
            pack_half2(o[nt][0] * inv0, o[nt][1] * inv0);
        ((uint32_t*)attn_out)[(((size_t)bb * SEQ + row0 + 8) * D_MODEL + d)/2] =
            pack_half2(o[nt][2] * inv1, o[nt][3] * inv1);
    }
}

// ---------------------------------------------------------------------------

static const int ATTN_SMEM = 4 * KTU * (int)sizeof(uint32_t);               // 36864
static const int GEMM_SMEM = (2*ABUF + 2*BBUF) * (int)sizeof(uint32_t);     // 55296

extern "C" void kernel_launch(void* const* d_in, const int* in_sizes, int n_in,
                              void* d_out, int out_size)
{
    const float* x     = (const float*)d_in[0];
    const float* W_qkv = (const float*)d_in[1];
    const float* b_qkv = (const float*)d_in[2];
    const float* W_out = (const float*)d_in[3];
    const float* b_out = (const float*)d_in[4];
    float* out = (float*)d_out;

    cudaFuncSetAttribute(attn_kernel,
                         cudaFuncAttributeMaxDynamicSharedMemorySize, ATTN_SMEM);
    cudaFuncSetAttribute(mma_gemm_kernel<0>,
                         cudaFuncAttributeMaxDynamicSharedMemorySize, GEMM_SMEM);
    cudaFuncSetAttribute(mma_gemm_kernel<1>,
                         cudaFuncAttributeMaxDynamicSharedMemorySize, GEMM_SMEM);

    __half *xh, *wqkv_t, *wout_t, *attn_h;
    cudaGetSymbolAddress((void**)&xh, g_h);
    cudaGetSymbolAddress((void**)&wqkv_t, g_wqkv_t);
    cudaGetSymbolAddress((void**)&wout_t, g_wout_t);
    attn_h = xh;   // reuse: X consumed by qkv gemm before attn writes

    convert_x_kernel<<<M_TOTAL*D_MODEL/(4*256), 256>>>(x, xh);
    transpose_w_kernel<<<dim3(N_QKV/32, KDIM/32), dim3(32, 8)>>>(W_qkv, wqkv_t, KDIM, N_QKV);
    transpose_w_kernel<<<dim3(D_MODEL/32, KDIM/32), dim3(32, 8)>>>(W_out, wout_t, KDIM, D_MODEL);

    dim3 g1(N_QKV / 128, M_TOTAL / 64);      // 18 x 128
    mma_gemm_kernel<0><<<g1, 128, GEMM_SMEM>>>(xh, wqkv_t, b_qkv, nullptr);

    dim3 g2(SEQ / 64, BH);                   // 32 x 48
    attn_kernel<<<g2, 128, ATTN_SMEM>>>(attn_h);

    dim3 g3(D_MODEL / 128, M_TOTAL / 64);    // 6 x 128
    mma_gemm_kernel<1><<<g3, 128, GEMM_SMEM>>>(attn_h, wout_t, b_out, out);
}

// round 17
// speedup vs baseline: 1.0448x; 1.0448x over previous
#include <cuda_runtime.h>
#include <cuda_fp16.h>
#include <math.h>
#include <stdint.h>

#define D_MODEL 768
#define HEADS   12
#define HD      64
#define BATCH   4
#define SEQ     2048
#define M_TOTAL (BATCH*SEQ)      // 8192
#define N_QKV   (3*D_MODEL)      // 2304
#define BH      (BATCH*HEADS)    // 48
#define KDIM    768
#define NCHUNK  (KDIM/64)        // 12 chunks of K=64

// q scale: 1/sqrt(64) * log2(e)  (softmax done in exp2 domain)
#define QSCALE 0.1803368801111306f
#define ONES2  0x3C003C00u       // half2(1.0, 1.0)

// Scratch (device globals)
__device__ __half g_q[BH*SEQ*HD];       // pre-scaled by QSCALE
__device__ __half g_k[BH*SEQ*HD];
__device__ __half g_vt[BH*HD*SEQ];      // [bh][d][seq]
__device__ __half g_h[M_TOTAL*D_MODEL]; // half X, later attn output
__device__ __half g_wqkv_t[N_QKV*KDIM];
__device__ __half g_wout_t[D_MODEL*KDIM];

// ---------------------------------------------------------------------------
__device__ __forceinline__ uint32_t smem_to_u32(const void* p) {
    uint32_t a;
    asm("{ .reg .u64 t; cvta.to.shared.u64 t, %1; cvt.u32.u64 %0, t; }"
        : "=r"(a) : "l"(p));
    return a;
}
__device__ __forceinline__ uint32_t pack_half2(float lo, float hi) {
    uint32_t u;
    asm("cvt.rn.f16x2.f32 %0, %1, %2;" : "=r"(u) : "f"(hi), "f"(lo));
    return u;
}
__device__ __forceinline__ uint32_t exp2_h2(uint32_t a) {
    uint32_t d;
    asm("ex2.approx.f16x2 %0, %1;" : "=r"(d) : "r"(a));
    return d;
}
__device__ __forceinline__ void ldsm_x4(uint32_t& r0, uint32_t& r1,
                                        uint32_t& r2, uint32_t& r3, uint32_t addr)
{
    asm volatile("ldmatrix.sync.aligned.m8n8.x4.shared.b16 {%0,%1,%2,%3}, [%4];"
        : "=r"(r0), "=r"(r1), "=r"(r2), "=r"(r3) : "r"(addr));
}
#define CP_ASYNC16(smem_addr, gptr) \
    asm volatile("cp.async.cg.shared.global [%0], [%1], 16;" \
        :: "r"(smem_addr), "l"(gptr))
#define CP_COMMIT() asm volatile("cp.async.commit_group;" ::: "memory")
#define CP_WAIT1()  asm volatile("cp.async.wait_group 1;" ::: "memory")
#define CP_WAIT0()  asm volatile("cp.async.wait_group 0;" ::: "memory")

__device__ __forceinline__ void mma_f16(float c[4],
    uint32_t a0, uint32_t a1, uint32_t a2, uint32_t a3,
    uint32_t b0, uint32_t b1)
{
    asm volatile(
        "mma.sync.aligned.m16n8k16.row.col.f32.f16.f16.f32 "
        "{%0,%1,%2,%3}, {%4,%5,%6,%7}, {%8,%9}, {%0,%1,%2,%3};"
        : "+f"(c[0]), "+f"(c[1]), "+f"(c[2]), "+f"(c[3])
        : "r"(a0), "r"(a1), "r"(a2), "r"(a3), "r"(b0), "r"(b1));
}

// ---------------------------------------------------------------------------
// X -> half
__global__ void convert_x_kernel(const float* __restrict__ src, __half* __restrict__ dst)
{
    const int i = (blockIdx.x * blockDim.x + threadIdx.x) * 4;
    float4 v = *(const float4*)&src[i];
    ((uint32_t*)dst)[i/2]     = pack_half2(v.x, v.y);
    ((uint32_t*)dst)[i/2 + 1] = pack_half2(v.z, v.w);
}

// Both weight transposes in ONE launch. z=0: W_qkv [768 x 2304] -> g_wqkv_t.
// z=1: W_out [768 x 768] -> g_wout_t (only blockIdx.x < 24 participate).
__global__ void transpose_w_kernel(const float* __restrict__ wqkv,
                                   const float* __restrict__ wout)
{
    __shared__ float t[32][33];
    const int z = blockIdx.z;
    if (z == 1 && blockIdx.x >= D_MODEL/32) return;
    const int C = (z == 0) ? N_QKV : D_MODEL;
    const float* src = (z == 0) ? wqkv : wout;
    __half* dst = (z == 0) ? g_wqkv_t : g_wout_t;

    const int bx = blockIdx.x * 32, by = blockIdx.y * 32;
    const int x = threadIdx.x, y = threadIdx.y;
    #pragma unroll
    for (int i = 0; i < 32; i += 8)
        t[y + i][x] = src[(size_t)(by + y + i) * C + bx + x];
    __syncthreads();
    #pragma unroll
    for (int i = 0; i < 32; i += 8)
        dst[(size_t)(bx + y + i) * KDIM + by + x] = __float2half_rn(t[x][y + i]);
}

// ---------------------------------------------------------------------------
// fp16 mma.sync GEMM: 128-thread CTAs (4 warps), tile 64m x 128n, 4 CTAs/SM.
// 2-stage cp.async, K chunks of 64, ldmatrix fragments. (R14, unchanged)
// MODE 0: scatter q(*QSCALE)/k to [bh][seq][64]; V transposed into g_vt.
// MODE 1: fp32 [M][768] out.
// ---------------------------------------------------------------------------
#define HPU   36                 // u32 per smem row (72 halfs, 64 used)
#define ABUF  (64*HPU)           // A stage: 2304 u32
#define BBUF  (128*HPU)          // B stage: 4608 u32
#define CPITCH 133               // floats, epilogue staging pitch

template<int MODE>
__global__ __launch_bounds__(128, 4)
void mma_gemm_kernel(const __half* __restrict__ A, const __half* __restrict__ Bt,
                     const float* __restrict__ bias, float* __restrict__ out)
{
    extern __shared__ uint32_t smu[];
    float* smf = (float*)smu;

    const int tid  = threadIdx.x;
    const int wid  = tid >> 5;
    const int lane = tid & 31;
    const int m0 = blockIdx.y * 64;
    const int n0 = blockIdx.x * 128;
    const int wm = (wid >> 1) * 32;
    const int wn = (wid & 1) * 64;
    const uint32_t sbase = smem_to_u32(smu);
    const int r = lane >> 2;
    const int cl = lane & 3;
    const int mm = lane >> 3;
    const int lrow = lane & 7;

    uint32_t aoff[2], boff[4];
    #pragma unroll
    for (int mi = 0; mi < 2; mi++)
        aoff[mi] = ((wm + mi*16 + (mm & 1)*8 + lrow) * HPU + (mm >> 1)*4) * 4;
    #pragma unroll
    for (int p = 0; p < 4; p++)
        boff[p] = ((wn + (p*2 + (mm >> 1))*8 + lrow) * HPU + (mm & 1)*4) * 4;

    float acc[2][8][4] = {};

    #pragma unroll
    for (int i = 0; i < 12; i++) {
        const int idx = i * 128 + tid;
        if (idx < 512) {
            const int row = idx >> 3;
            const int seg = (idx & 7) * 8;
            CP_ASYNC16(sbase + (uint32_t)(row*HPU)*4 + seg*2,
                       &A[(size_t)(m0 + row) * KDIM + seg]);
        } else {
            const int j = idx - 512;
            const int row = j >> 3;
            const int seg = (j & 7) * 8;
            CP_ASYNC16(sbase + (uint32_t)(2*ABUF + row*HPU)*4 + seg*2,
                       &Bt[(size_t)(n0 + row) * KDIM + seg]);
        }
    }
    CP_COMMIT();

    for (int c = 0; c < NCHUNK; c++) {
        const int buf = c & 1;
        if (c + 1 < NCHUNK) {
            const int nb = buf ^ 1;
            const int k0 = (c + 1) * 64;
            #pragma unroll
            for (int i = 0; i < 12; i++) {
                const int idx = i * 128 + tid;
                if (idx < 512) {
                    const int row = idx >> 3;
                    const int seg = (idx & 7) * 8;
                    CP_ASYNC16(sbase + (uint32_t)(nb*ABUF + row*HPU)*4 + seg*2,
                               &A[(size_t)(m0 + row) * KDIM + k0 + seg]);
                } else {
                    const int j = idx - 512;
                    const int row = j >> 3;
                    const int seg = (j & 7) * 8;
                    CP_ASYNC16(sbase + (uint32_t)(2*ABUF + nb*BBUF + row*HPU)*4 + seg*2,
                               &Bt[(size_t)(n0 + row) * KDIM + k0 + seg]);
                }
            }
            CP_COMMIT();
            CP_WAIT1();
        } else {
            CP_WAIT0();
        }
        __syncthreads();

        const uint32_t aB = sbase + (uint32_t)(buf*ABUF)*4;
        const uint32_t bB = sbase + (uint32_t)(2*ABUF + buf*BBUF)*4;

        #pragma unroll
        for (int ks = 0; ks < 4; ks++) {
            const uint32_t kbyte = ks * 32;
            uint32_t af[2][4];
            #pragma unroll
            for (int mi = 0; mi < 2; mi++)
                ldsm_x4(af[mi][0], af[mi][1], af[mi][2], af[mi][3],
                        aB + aoff[mi] + kbyte);
            uint32_t bf[8][2];
            #pragma unroll
            for (int p = 0; p < 4; p++)
                ldsm_x4(bf[2*p][0], bf[2*p][1], bf[2*p+1][0], bf[2*p+1][1],
                        bB + boff[p] + kbyte);
            #pragma unroll
            for (int mi = 0; mi < 2; mi++)
                #pragma unroll
                for (int ni = 0; ni < 8; ni++)
                    mma_f16(acc[mi][ni], af[mi][0], af[mi][1], af[mi][2], af[mi][3],
                            bf[ni][0], bf[ni][1]);
        }
        __syncthreads();
    }

    #pragma unroll
    for (int mi = 0; mi < 2; mi++)
        #pragma unroll
        for (int ni = 0; ni < 8; ni++) {
            const int row = wm + mi*16 + r;
            const int col = wn + ni*8 + 2*cl;
            smf[row * CPITCH + col]       = acc[mi][ni][0];
            smf[row * CPITCH + col + 1]   = acc[mi][ni][1];
            smf[(row+8) * CPITCH + col]   = acc[mi][ni][2];
            smf[(row+8) * CPITCH + col+1] = acc[mi][ni][3];
        }
    __syncthreads();

    if (MODE == 1) {
        #pragma unroll
        for (int i = 0; i < 16; i++) {
            const int f = i * 128 + tid;
            const int row  = f >> 5;
            const int col  = (f & 31) * 4;
            const int m  = m0 + row;
            const int ng = n0 + col;
            float4 v = { smf[row*CPITCH + col + 0] + bias[ng + 0],
                         smf[row*CPITCH + col + 1] + bias[ng + 1],
                         smf[row*CPITCH + col + 2] + bias[ng + 2],
                         smf[row*CPITCH + col + 3] + bias[ng + 3] };
            *(float4*)&out[(size_t)m * D_MODEL + ng] = v;
        }
    } else {
        const int wsel = n0 / D_MODEL;
        if (wsel < 2) {
            __half* dst = (wsel == 0) ? g_q : g_k;
            const float sc = (wsel == 0) ? QSCALE : 1.0f;
            #pragma unroll
            for (int i = 0; i < 16; i++) {
                const int f = i * 128 + tid;
                const int row  = f >> 5;
                const int col  = (f & 31) * 4;
                const int m  = m0 + row;
                const int ng = n0 + col;
                float4 v = { (smf[row*CPITCH + col + 0] + bias[ng + 0]) * sc,
                             (smf[row*CPITCH + col + 1] + bias[ng + 1]) * sc,
                             (smf[row*CPITCH + col + 2] + bias[ng + 2]) * sc,
                             (smf[row*CPITCH + col + 3] + bias[ng + 3]) * sc };
                const int h = (ng % D_MODEL) >> 6;
                const int d = ng & 63;
                const int bb = m >> 11;
                const int l  = m & (SEQ - 1);
                const size_t off = (((size_t)bb * HEADS + h) * SEQ + l) * HD + d;
                ((uint32_t*)dst)[off/2]     = pack_half2(v.x, v.y);
                ((uint32_t*)dst)[off/2 + 1] = pack_half2(v.z, v.w);
            }
        } else {
            const int bb = m0 >> 11;
            const int l0 = m0 & (SEQ - 1);
            #pragma unroll
            for (int it = 0; it < 32; it++) {
                const int idx = it * 128 + tid;
                const int d  = idx >> 5;
                const int l2 = idx & 31;
                const int ng = n0 + d;
                const float bv = bias[ng];
                const int h  = (ng % D_MODEL) >> 6;
                const int dd = ng & 63;
                const float v0 = smf[(2*l2)   * CPITCH + d] + bv;
                const float v1 = smf[(2*l2+1) * CPITCH + d] + bv;
                const size_t off = ((size_t)(bb * HEADS + h) * HD + dd) * SEQ + l0 + 2*l2;
                ((uint32_t*)g_vt)[off/2] = pack_half2(v0, v1);
            }
        }
    }
}

// ---------------------------------------------------------------------------
// Flash attention: 128-thread CTAs (4 warps x 16q = 64 q rows), 4 CTAs/SM.
// 64-key tiles double-buffered. K smem [key][d], VT [d][key], pitch 72h.
// f16x2 exp2 softmax, ones-MMA row sums, P in registers. (R14, unchanged)
// ---------------------------------------------------------------------------
#define AKPU  36                 // u32 per 72-half row
#define KTU   (64*AKPU)          // 2304 u32 per K or VT tile

__global__ __launch_bounds__(128, 4) void attn_kernel(__half* __restrict__ attn_out)
{
    extern __shared__ uint32_t smA[];

    const int tid  = threadIdx.x;
    const int wid  = tid >> 5;
    const int lane = tid & 31;
    const int r  = lane >> 2;
    const int cl = lane & 3;
    const int mm = lane >> 3;
    const int lrow = lane & 7;
    const int qt = blockIdx.x;
    const int bh = blockIdx.y;
    const size_t head_base = (size_t)bh * SEQ * HD;   // halfs
    const int q0 = wid * 16;

    uint32_t foff[4];
    #pragma unroll
    for (int p = 0; p < 4; p++)
        foff[p] = (((p*2 + (mm >> 1))*8 + lrow) * AKPU + (mm & 1)*4) * 4;

    // Q fragments (g_q pre-scaled): 4 ksteps x 4 regs
    uint32_t qf[4][4];
    {
        const uint32_t* Qp = (const uint32_t*)&g_q[head_base + (size_t)(qt*64 + q0) * HD];
        #pragma unroll
        for (int kk = 0; kk < 4; kk++) {
            qf[kk][0] = Qp[(size_t)r     * 32 + kk*8 + cl];
            qf[kk][1] = Qp[(size_t)(r+8) * 32 + kk*8 + cl];
            qf[kk][2] = Qp[(size_t)r     * 32 + kk*8 + cl + 4];
            qf[kk][3] = Qp[(size_t)(r+8) * 32 + kk*8 + cl + 4];
        }
    }

    float o[8][4] = {};
    float mo0 = -INFINITY, mo1 = -INFINITY, lo0 = 0.0f, lo1 = 0.0f;

    const uint32_t sb = smem_to_u32(smA);
    // layout: [K0, V0, K1, V1]
    const uint32_t kb[2] = { sb,              sb + 2*KTU*4 };
    const uint32_t vb[2] = { sb + KTU*4,      sb + 3*KTU*4 };
    const size_t vt_base = (size_t)bh * HD * SEQ;

    // prologue tile 0: K 64x8 segs (512) + VT 64x8 segs (512) = 8/thread
    #pragma unroll
    for (int i = 0; i < 8; i++) {
        const int idx = i * 128 + tid;
        if (idx < 512) {
            const int row = idx >> 3;
            const int seg = (idx & 7) * 8;
            CP_ASYNC16(kb[0] + (uint32_t)(row*AKPU)*4 + seg*2,
                       (const char*)&g_k[head_base + (size_t)row * HD + seg]);
        } else {
            const int j = idx - 512;
            const int row = j >> 3;
            const int seg = (j & 7) * 8;
            CP_ASYNC16(vb[0] + (uint32_t)(row*AKPU)*4 + seg*2,
                       (const char*)&g_vt[vt_base + (size_t)row * SEQ + seg]);
        }
    }
    CP_COMMIT();

    for (int kt = 0; kt < SEQ/64; kt++) {
        const int buf = kt & 1;
        __syncthreads();   // done with buf^1
        if (kt + 1 < SEQ/64) {
            const int nb = buf ^ 1;
            #pragma unroll
            for (int i = 0; i < 8; i++) {
                const int idx = i * 128 + tid;
                if (idx < 512) {
                    const int row = idx >> 3;
                    const int seg = (idx & 7) * 8;
                    CP_ASYNC16(kb[nb] + (uint32_t)(row*AKPU)*4 + seg*2,
                               (const char*)&g_k[head_base + (size_t)((kt+1)*64 + row) * HD + seg]);
                } else {
                    const int j = idx - 512;
                    const int row = j >> 3;
                    const int seg = (j & 7) * 8;
                    CP_ASYNC16(vb[nb] + (uint32_t)(row*AKPU)*4 + seg*2,
                               (const char*)&g_vt[vt_base + (size_t)row * SEQ + (kt+1)*64 + seg]);
                }
            }
            CP_COMMIT();
            CP_WAIT1();
        } else {
            CP_WAIT0();
        }
        __syncthreads();   // tile kt visible

        // ---- S = Q K^T ----
        const uint32_t Kc = kb[buf];
        float s[8][4] = {};
        #pragma unroll
        for (int kk = 0; kk < 4; kk++) {
            const uint32_t kbyte = kk * 32;
            uint32_t bf[8][2];
            #pragma unroll
            for (int p = 0; p < 4; p++)
                ldsm_x4(bf[2*p][0], bf[2*p][1], bf[2*p+1][0], bf[2*p+1][1],
                        Kc + foff[p] + kbyte);
            #pragma unroll
            for (int nt = 0; nt < 8; nt++)
                mma_f16(s[nt], qf[kk][0], qf[kk][1], qf[kk][2], qf[kk][3],
                        bf[nt][0], bf[nt][1]);
        }

        // ---- row max (quad reduction) ----
        float mx0 = -INFINITY, mx1 = -INFINITY;
        #pragma unroll
        for (int nt = 0; nt < 8; nt++) {
            mx0 = fmaxf(mx0, fmaxf(s[nt][0], s[nt][1]));
            mx1 = fmaxf(mx1, fmaxf(s[nt][2], s[nt][3]));
        }
        mx0 = fmaxf(mx0, __shfl_xor_sync(0xffffffffu, mx0, 1));
        mx0 = fmaxf(mx0, __shfl_xor_sync(0xffffffffu, mx0, 2));
        mx1 = fmaxf(mx1, __shfl_xor_sync(0xffffffffu, mx1, 1));
        mx1 = fmaxf(mx1, __shfl_xor_sync(0xffffffffu, mx1, 2));
        const float mn0 = fmaxf(mo0, mx0);
        const float mn1 = fmaxf(mo1, mx1);
        const float a0 = exp2f(mo0 - mn0);
        const float a1 = exp2f(mo1 - mn1);

        // ---- P = exp2(s - m) in f16x2, packed as PV A-fragments ----
        uint32_t pf[4][4];
        #pragma unroll
        for (int kk = 0; kk < 4; kk++) {
            pf[kk][0] = exp2_h2(pack_half2(s[2*kk][0]   - mn0, s[2*kk][1]   - mn0));
            pf[kk][1] = exp2_h2(pack_half2(s[2*kk][2]   - mn1, s[2*kk][3]   - mn1));
            pf[kk][2] = exp2_h2(pack_half2(s[2*kk+1][0] - mn0, s[2*kk+1][1] - mn0));
            pf[kk][3] = exp2_h2(pack_half2(s[2*kk+1][2] - mn1, s[2*kk+1][3] - mn1));
        }

        // ---- row sums via ones-MMA ----
        float ls[4] = {};
        #pragma unroll
        for (int kk = 0; kk < 4; kk++)
            mma_f16(ls, pf[kk][0], pf[kk][1], pf[kk][2], pf[kk][3], ONES2, ONES2);

        lo0 = a0 * lo0 + ls[0];  mo0 = mn0;
        lo1 = a1 * lo1 + ls[2];  mo1 = mn1;
        #pragma unroll
        for (int nt = 0; nt < 8; nt++) {
            o[nt][0] *= a0; o[nt][1] *= a0;
            o[nt][2] *= a1; o[nt][3] *= a1;
        }

        // ---- O += P V ----
        const uint32_t Vc = vb[buf];
        #pragma unroll
        for (int kk = 0; kk < 4; kk++) {
            const uint32_t kbyte = kk * 32;
            uint32_t bf[8][2];
            #pragma unroll
            for (int p = 0; p < 4; p++)
                ldsm_x4(bf[2*p][0], bf[2*p][1], bf[2*p+1][0], bf[2*p+1][1],
                        Vc + foff[p] + kbyte);
            #pragma unroll
            for (int nt = 0; nt < 8; nt++)
                mma_f16(o[nt], pf[kk][0], pf[kk][1], pf[kk][2], pf[kk][3],
                        bf[nt][0], bf[nt][1]);
        }
    }

    // ---- epilogue: normalize, write half [B, L, H*64] ----
    const float inv0 = 1.0f / lo0;
    const float inv1 = 1.0f / lo1;
    const int bb = bh / HEADS;
    const int h  = bh % HEADS;
    const int row0 = qt*64 + q0 + r;
    #pragma unroll
    for (int nt = 0; nt < 8; nt++) {
        const int d = h * 64 + nt*8 + 2*cl;
        ((uint32_t*)attn_out)[(((size_t)bb * SEQ + row0)     * D_MODEL + d)/2] =
            pack_half2(o[nt][0] * inv0, o[nt][1] * inv0);
        ((uint32_t*)attn_out)[(((size_t)bb * SEQ + row0 + 8) * D_MODEL + d)/2] =
            pack_half2(o[nt][2] * inv1, o[nt][3] * inv1);
    }
}

// ---------------------------------------------------------------------------

static const int ATTN_SMEM = 4 * KTU * (int)sizeof(uint32_t);               // 36864
static const int GEMM_SMEM = (2*ABUF + 2*BBUF) * (int)sizeof(uint32_t);     // 55296

extern "C" void kernel_launch(void* const* d_in, const int* in_sizes, int n_in,
                              void* d_out, int out_size)
{
    const float* x     = (const float*)d_in[0];
    const float* W_qkv = (const float*)d_in[1];
    const float* b_qkv = (const float*)d_in[2];
    const float* W_out = (const float*)d_in[3];
    const float* b_out = (const float*)d_in[4];
    float* out = (float*)d_out;

    cudaFuncSetAttribute(attn_kernel,
                         cudaFuncAttributeMaxDynamicSharedMemorySize, ATTN_SMEM);
    cudaFuncSetAttribute(mma_gemm_kernel<0>,
                         cudaFuncAttributeMaxDynamicSharedMemorySize, GEMM_SMEM);
    cudaFuncSetAttribute(mma_gemm_kernel<1>,
                         cudaFuncAttributeMaxDynamicSharedMemorySize, GEMM_SMEM);

    __half *xh, *attn_h;
    cudaGetSymbolAddress((void**)&xh, g_h);
    attn_h = xh;   // reuse: X consumed by qkv gemm before attn writes

    __half *wqkv_t, *wout_t;
    cudaGetSymbolAddress((void**)&wqkv_t, g_wqkv_t);
    cudaGetSymbolAddress((void**)&wout_t, g_wout_t);

    convert_x_kernel<<<M_TOTAL*D_MODEL/(4*256), 256>>>(x, xh);
    // fused: z=0 transposes W_qkv, z=1 transposes W_out
    transpose_w_kernel<<<dim3(N_QKV/32, KDIM/32, 2), dim3(32, 8)>>>(W_qkv, W_out);

    dim3 g1(N_QKV / 128, M_TOTAL / 64);      // 18 x 128
    mma_gemm_kernel<0><<<g1, 128, GEMM_SMEM>>>(xh, wqkv_t, b_qkv, nullptr);

    dim3 g2(SEQ / 64, BH);                   // 32 x 48
    attn_kernel<<<g2, 128, ATTN_SMEM>>>(attn_h);

    dim3 g3(D_MODEL / 128, M_TOTAL / 64);    // 6 x 128
    mma_gemm_kernel<1><<<g3, 128, GEMM_SMEM>>>(attn_h, wout_t, b_out, out);
}